// round 1
// baseline (speedup 1.0000x reference)
#include <cuda_runtime.h>
#include <math.h>

#define TTOT 50

// ---------------- constants / weights ----------------
__device__ float g_psp[32];
__device__ float g_ref[16];
__constant__ float c_wts[6160];   // w1 @0 (400), w2 @400 (1152), w3 @1552 (4608)

// ---------------- scratch (time-planar [T][N][C][H][W]) ----------------
__device__ float g_buf0[26214400];   // [50][4][2][256][256]
__device__ float g_buf1[25806400];   // [50][4][8][127][127]
__device__ float g_buf2[6350400];    // [50][4][8][63][63]
__device__ float g_buf3[3276800];    // [50][4][16][32][32]
__device__ float g_buf4[819200];     // [50][4][16][16][16]
__device__ float g_buf5[409600];     // [50][4][32][8][8]

// ---------------- init: fp64 kernel constants (match numpy) ----------------
__global__ void init_consts() {
    int i = threadIdx.x;
    if (i < 32) g_psp[i] = (float)((i / 10.0) * exp(1.0 - i / 10.0));
    if (i < 16) g_ref[i] = (float)(-20.0 * (double)(i + 1) * exp(-(double)i));
}

// ---------------- psp0: [N,C,H,W,T] -> planar, 32-tap FIR ----------------
__global__ void psp0_kernel(const float* __restrict__ in, float* __restrict__ out) {
    int n = blockIdx.x * blockDim.x + threadIdx.x;
    if (n >= 524288) return;
    float kp[32];
#pragma unroll
    for (int k = 0; k < 32; k++) kp[k] = g_psp[k];
    float x[TTOT];
    const float* p = in + (size_t)n * TTOT;
#pragma unroll
    for (int t = 0; t < TTOT; t++) x[t] = __ldg(p + t);
#pragma unroll
    for (int t = 0; t < TTOT; t++) {
        float acc = 0.f;
#pragma unroll
        for (int k = 1; k < 32; k++)
            if (k <= t) acc = fmaf(kp[k], x[t - k], acc);
        out[t * 524288 + n] = acc;
    }
}

// ---------------- psp in-place on planar buffer, stride S ----------------
__global__ void psp_kernel(float* __restrict__ buf, int S) {
    int n = blockIdx.x * blockDim.x + threadIdx.x;
    if (n >= S) return;
    float kp[32];
#pragma unroll
    for (int k = 0; k < 32; k++) kp[k] = g_psp[k];
    float x[TTOT];
#pragma unroll
    for (int t = 0; t < TTOT; t++) x[t] = buf[(size_t)t * S + n];
#pragma unroll
    for (int t = 0; t < TTOT; t++) {
        float acc = 0.f;
#pragma unroll
        for (int k = 1; k < 32; k++)
            if (k <= t) acc = fmaf(kp[k], x[t - k], acc);
        buf[(size_t)t * S + n] = acc;
    }
}

// ---------------- spike: sequential threshold + refractory ring ----------------
__global__ void spike_kernel(float* __restrict__ buf, int S) {
    int n = blockIdx.x * blockDim.x + threadIdx.x;
    if (n >= S) return;
    float rf[16];
#pragma unroll
    for (int j = 0; j < 16; j++) rf[j] = g_ref[j];
    float rb[16];
#pragma unroll
    for (int j = 0; j < 16; j++) rb[j] = 0.f;
#pragma unroll
    for (int t = 0; t < TTOT; t++) {
        float v = buf[(size_t)t * S + n] + rb[t & 15];
        rb[t & 15] = 0.f;
        float s;
        if (v >= 10.0f) {
            s = 1.0f;
#pragma unroll
            for (int j = 0; j < 16; j++) rb[(t + 1 + j) & 15] += rf[j];
        } else {
            s = 0.0f;
        }
        buf[(size_t)t * S + n] = s;
    }
}

// ---------------- conv: stride-2, pad-1; register-tiled COG x WT ----------------
template<int CI, int CO, int COG, int HI, int HO, int K, int WOFF, int WT>
__global__ void conv_kernel(const float* __restrict__ in, float* __restrict__ out) {
    constexpr int WOT  = (HO + WT - 1) / WT;
    constexpr int NCOG = CO / COG;
    constexpr int NV   = 2 * (WT - 1) + K;
    constexpr int TOTAL = 200 * NCOG * HO * WOT;   // 200 = T*N
    int idx = blockIdx.x * blockDim.x + threadIdx.x;
    if (idx >= TOTAL) return;
    int wt  = idx % WOT;
    int r   = idx / WOT;
    int ho  = r % HO;  r /= HO;
    int cog = r % NCOG; r /= NCOG;
    int img = r;
    int wo0 = wt * WT;
    const float* inb = in + (size_t)img * CI * HI * HI;

    float acc[COG][WT];
#pragma unroll
    for (int c = 0; c < COG; c++)
#pragma unroll
        for (int j = 0; j < WT; j++) acc[c][j] = 0.f;

#pragma unroll
    for (int ci = 0; ci < CI; ci++) {
#pragma unroll
        for (int kh = 0; kh < K; kh++) {
            int ih = 2 * ho - 1 + kh;
            if (ih < 0 || ih >= HI) continue;
            const float* row = inb + (size_t)(ci * HI + ih) * HI;
            float xv[NV];
#pragma unroll
            for (int v = 0; v < NV; v++) {
                int iw = 2 * wo0 - 1 + v;
                xv[v] = (iw >= 0 && iw < HI) ? __ldg(row + iw) : 0.f;
            }
#pragma unroll
            for (int kw = 0; kw < K; kw++) {
#pragma unroll
                for (int c = 0; c < COG; c++) {
                    float w = c_wts[WOFF + (((cog * COG + c) * CI + ci) * K + kh) * K + kw];
#pragma unroll
                    for (int j = 0; j < WT; j++)
                        acc[c][j] = fmaf(xv[2 * j + kw], w, acc[c][j]);
                }
            }
        }
    }
#pragma unroll
    for (int c = 0; c < COG; c++) {
        int co = cog * COG + c;
        size_t ob = ((size_t)(img * CO + co) * HO + ho) * HO;
#pragma unroll
        for (int j = 0; j < WT; j++)
            if (wo0 + j < HO) out[ob + wo0 + j] = acc[c][j];
    }
}

// ---------------- 2x2/s2 sum-pool * 2.75 ----------------
template<int HI, int HO>
__global__ void pool_kernel(const float* __restrict__ in, float* __restrict__ out, int planes) {
    int idx = blockIdx.x * blockDim.x + threadIdx.x;
    int total = planes * HO * HO;
    if (idx >= total) return;
    int wo = idx % HO;
    int ho = (idx / HO) % HO;
    int c  = idx / (HO * HO);
    const float* p = in + (size_t)c * HI * HI + (size_t)(2 * ho) * HI + 2 * wo;
    out[idx] = 2.75f * ((p[0] + p[1]) + (p[HI] + p[HI + 1]));
}

// ---------------- FC head: one warp per (n,o,t) ----------------
__global__ void fc_kernel(const float* __restrict__ u, const float* __restrict__ wfc,
                          float* __restrict__ out) {
    int gw   = (blockIdx.x * blockDim.x + threadIdx.x) >> 5;
    int lane = threadIdx.x & 31;
    if (gw >= 400) return;
    int t  = gw % 50;
    int no = gw / 50;            // n*2+o
    int o  = no & 1;
    int n  = no >> 1;
    const float* ub = u + t * 8192 + n * 2048;
    const float* wb = wfc + o * 2048;
    float acc = 0.f;
#pragma unroll 8
    for (int i = lane; i < 2048; i += 32)
        acc = fmaf(__ldg(ub + i), __ldg(wb + i), acc);
#pragma unroll
    for (int off = 16; off; off >>= 1) acc += __shfl_xor_sync(0xffffffffu, acc, off);
    if (lane == 0) out[no * 50 + t] = acc;
}

// ---------------- final spike, in-place on d_out ([n][o][t]) ----------------
__global__ void spike_last_kernel(float* __restrict__ buf) {
    int n = threadIdx.x;
    if (n >= 8) return;
    float rf[16];
#pragma unroll
    for (int j = 0; j < 16; j++) rf[j] = g_ref[j];
    float rb[16];
#pragma unroll
    for (int j = 0; j < 16; j++) rb[j] = 0.f;
    float* p = buf + n * 50;
#pragma unroll
    for (int t = 0; t < TTOT; t++) {
        float v = p[t] + rb[t & 15];
        rb[t & 15] = 0.f;
        float s;
        if (v >= 10.0f) {
            s = 1.0f;
#pragma unroll
            for (int j = 0; j < 16; j++) rb[(t + 1 + j) & 15] += rf[j];
        } else {
            s = 0.0f;
        }
        p[t] = s;
    }
}

static inline int cdiv(int a, int b) { return (a + b - 1) / b; }

extern "C" void kernel_launch(void* const* d_in, const int* in_sizes, int n_in,
                              void* d_out, int out_size) {
    const float* x_in = (const float*)d_in[0];
    const float* wfc  = (const float*)d_in[4];

    float *b0, *b1, *b2, *b3, *b4, *b5;
    cudaGetSymbolAddress((void**)&b0, g_buf0);
    cudaGetSymbolAddress((void**)&b1, g_buf1);
    cudaGetSymbolAddress((void**)&b2, g_buf2);
    cudaGetSymbolAddress((void**)&b3, g_buf3);
    cudaGetSymbolAddress((void**)&b4, g_buf4);
    cudaGetSymbolAddress((void**)&b5, g_buf5);

    // weights -> constant memory (D2D, graph-capturable)
    cudaMemcpyToSymbolAsync(c_wts, d_in[1], 400  * sizeof(float), 0,    cudaMemcpyDeviceToDevice, 0);
    cudaMemcpyToSymbolAsync(c_wts, d_in[2], 1152 * sizeof(float), 1600, cudaMemcpyDeviceToDevice, 0);
    cudaMemcpyToSymbolAsync(c_wts, d_in[3], 4608 * sizeof(float), 6208, cudaMemcpyDeviceToDevice, 0);

    init_consts<<<1, 32>>>();

    // L1: psp -> conv(2->8, k5 s2 p1, 256->127) -> spike
    psp0_kernel<<<cdiv(524288, 256), 256>>>(x_in, b0);
    conv_kernel<2, 8, 8, 256, 127, 5, 0, 4><<<cdiv(200 * 127 * 32, 256), 256>>>(b0, b1);
    spike_kernel<<<cdiv(516128, 256), 256>>>(b1, 516128);

    // L2: psp -> pool(127->63) -> spike
    psp_kernel<<<cdiv(516128, 256), 256>>>(b1, 516128);
    pool_kernel<127, 63><<<cdiv(1600 * 63 * 63, 256), 256>>>(b1, b2, 1600);
    spike_kernel<<<cdiv(127008, 256), 256>>>(b2, 127008);

    // L3: psp -> conv(8->16, k3 s2 p1, 63->32) -> spike
    psp_kernel<<<cdiv(127008, 256), 256>>>(b2, 127008);
    conv_kernel<8, 16, 16, 63, 32, 3, 400, 2><<<cdiv(200 * 32 * 16, 256), 256>>>(b2, b3);
    spike_kernel<<<cdiv(65536, 256), 256>>>(b3, 65536);

    // L4: psp -> pool(32->16) -> spike
    psp_kernel<<<cdiv(65536, 256), 256>>>(b3, 65536);
    pool_kernel<32, 16><<<cdiv(3200 * 16 * 16, 256), 256>>>(b3, b4, 3200);
    spike_kernel<<<cdiv(16384, 256), 256>>>(b4, 16384);

    // L5: psp -> conv(16->32, k3 s2 p1, 16->8) -> spike
    psp_kernel<<<cdiv(16384, 256), 256>>>(b4, 16384);
    conv_kernel<16, 32, 8, 16, 8, 3, 1552, 2><<<cdiv(200 * 4 * 8 * 4, 256), 256>>>(b4, b5);
    spike_kernel<<<cdiv(8192, 256), 256>>>(b5, 8192);

    // head: psp -> FC -> spike (in-place on d_out)
    psp_kernel<<<cdiv(8192, 256), 256>>>(b5, 8192);
    fc_kernel<<<100, 128>>>(b5, wfc, (float*)d_out);
    spike_last_kernel<<<1, 8>>>((float*)d_out);
}